// round 3
// baseline (speedup 1.0000x reference)
#include <cuda_runtime.h>

#define BB 256
#define NN 1000
#define DD 128
#define HH 8
#define NEGV (-1e9f)

// ---- packed f32x2 helpers (sm_103a) ----
static __device__ __forceinline__ unsigned long long packdup(float a) {
    unsigned long long r; unsigned int u = __float_as_uint(a);
    asm("mov.b64 %0, {%1, %2};" : "=l"(r) : "r"(u), "r"(u));
    return r;
}
static __device__ __forceinline__ unsigned long long fma2(unsigned long long a,
                                                          unsigned long long b,
                                                          unsigned long long c) {
    unsigned long long d;
    asm("fma.rn.f32x2 %0, %1, %2, %3;" : "=l"(d) : "l"(a), "l"(b), "l"(c));
    return d;
}
static __device__ __forceinline__ unsigned long long add2(unsigned long long a,
                                                          unsigned long long b) {
    unsigned long long d;
    asm("add.rn.f32x2 %0, %1, %2;" : "=l"(d) : "l"(a), "l"(b));
    return d;
}
static __device__ __forceinline__ float2 unpack2(unsigned long long v) {
    unsigned int lo, hi;
    asm("mov.b64 {%0, %1}, %2;" : "=r"(lo), "=r"(hi) : "l"(v));
    return make_float2(__uint_as_float(lo), __uint_as_float(hi));
}

__global__ __launch_bounds__(256) void attn_fused_kernel(
    const float* __restrict__ emb,        // [B, N, D]
    const float* __restrict__ Wn,         // [D, 3D]
    const float* __restrict__ Wf,         // [D, D]
    const float* __restrict__ Ws,         // [2D, D]
    const float* __restrict__ Wo,         // [D, D]
    const int*   __restrict__ fidx,       // [B]
    const int*   __restrict__ lidx,       // [B]
    const int*   __restrict__ mask,       // [B, N] bool stored as int32
    float* __restrict__ out)              // [B, N]
{
    __shared__ __align__(16) float s_compat[HH * NN];   // 32000 B (attn / logits scratch)
    __shared__ __align__(16) float s_QT[DD * HH];       // qtilde [d][h], scale folded
    __shared__ __align__(16) float s_ebar[HH * DD];     // attn-weighted emb sums (also phase-0 scratch)
    __shared__ __align__(16) float s_mean[DD];
    __shared__ __align__(16) float s_q[DD];
    __shared__ __align__(16) float s_ef[DD];
    __shared__ __align__(16) float s_el[DD];
    __shared__ __align__(16) float s_heads[DD];
    __shared__ __align__(16) float s_gl[DD];
    __shared__ __align__(16) float s_gt[DD];
    __shared__ float s_red[16];

    const int b = blockIdx.x;
    const int t = threadIdx.x;
    const int lane = t & 31;
    const int warp = t >> 5;
    const float* embB = emb + (size_t)b * NN * DD;
    const int* mkB = mask + (size_t)b * NN;

    // ---------------- Phase 0: graph mean + first/last rows ----------------
    {
        int d = t & 127, g = t >> 7;
        float a0 = 0.f, a1 = 0.f;
        int n = g;
        for (; n + 2 < NN; n += 4) {
            a0 += embB[(size_t)n * DD + d];
            a1 += embB[(size_t)(n + 2) * DD + d];
        }
        if (n < NN) a0 += embB[(size_t)n * DD + d];
        s_ebar[g * DD + d] = a0 + a1;   // scratch (two half-sums per dim)
    }
    {
        int fi = fidx[b], li = lidx[b];
        if (t < DD) s_ef[t] = embB[(size_t)fi * DD + t];
        else        s_el[t - DD] = embB[(size_t)li * DD + (t - DD)];
    }
    __syncthreads();
    if (t < DD) s_mean[t] = (s_ebar[t] + s_ebar[DD + t]) * (1.0f / NN);
    __syncthreads();

    // ---------------- Phase 0b: q = fixed_ctx + step_ctx @ W_step ----------
    if (t < DD) {
        float acc = 0.f;
        for (int i = 0; i < DD; i++) acc += s_mean[i] * Wf[i * DD + t];
        for (int i = 0; i < DD; i++) acc += s_ef[i] * Ws[i * DD + t];
        for (int i = 0; i < DD; i++) acc += s_el[i] * Ws[(DD + i) * DD + t];
        s_q[t] = acc;
    }
    __syncthreads();

    // ------------- Phase 0c: qtilde[d][h] = 0.25 * W_K[d, h-slice] . q_h ---
    {
        int d = t >> 1;
        int h0 = (t & 1) * 4;
        #pragma unroll
        for (int h = h0; h < h0 + 4; h++) {
            const float* w = Wn + d * 384 + h * 16;
            const float* qq = s_q + h * 16;
            float acc = 0.f;
            #pragma unroll
            for (int k = 0; k < 16; k++) acc += w[k] * qq[k];
            s_QT[d * HH + h] = acc * 0.25f;   // fold 1/sqrt(dk)
        }
    }
    __syncthreads();

    // ---------------- Phase 1: compat[h][n] = emb[n] . qtilde[:,h] ---------
    for (int n = t; n < NN; n += 256) {
        const float4* e4 = (const float4*)(embB + (size_t)n * DD);
        unsigned long long accA[4] = {0ull, 0ull, 0ull, 0ull};
        unsigned long long accB[4] = {0ull, 0ull, 0ull, 0ull};
        #pragma unroll 4
        for (int j = 0; j < 32; j++) {
            float4 e = e4[j];
            const ulonglong2* qt = (const ulonglong2*)(s_QT + j * 32); // rows 4j..4j+3
            unsigned long long ev;
            { ev = packdup(e.x); ulonglong2 qa = qt[0], qb = qt[1];
              accA[0] = fma2(ev, qa.x, accA[0]); accA[1] = fma2(ev, qa.y, accA[1]);
              accA[2] = fma2(ev, qb.x, accA[2]); accA[3] = fma2(ev, qb.y, accA[3]); }
            { ev = packdup(e.y); ulonglong2 qa = qt[2], qb = qt[3];
              accB[0] = fma2(ev, qa.x, accB[0]); accB[1] = fma2(ev, qa.y, accB[1]);
              accB[2] = fma2(ev, qb.x, accB[2]); accB[3] = fma2(ev, qb.y, accB[3]); }
            { ev = packdup(e.z); ulonglong2 qa = qt[4], qb = qt[5];
              accA[0] = fma2(ev, qa.x, accA[0]); accA[1] = fma2(ev, qa.y, accA[1]);
              accA[2] = fma2(ev, qb.x, accA[2]); accA[3] = fma2(ev, qb.y, accA[3]); }
            { ev = packdup(e.w); ulonglong2 qa = qt[6], qb = qt[7];
              accB[0] = fma2(ev, qa.x, accB[0]); accB[1] = fma2(ev, qa.y, accB[1]);
              accB[2] = fma2(ev, qb.x, accB[2]); accB[3] = fma2(ev, qb.y, accB[3]); }
        }
        float2 p0 = unpack2(add2(accA[0], accB[0]));
        float2 p1 = unpack2(add2(accA[1], accB[1]));
        float2 p2 = unpack2(add2(accA[2], accB[2]));
        float2 p3 = unpack2(add2(accA[3], accB[3]));
        float vals[8] = {p0.x, p0.y, p1.x, p1.y, p2.x, p2.y, p3.x, p3.y};
        bool m = mkB[n] != 0;
        #pragma unroll
        for (int h = 0; h < HH; h++) s_compat[h * NN + n] = m ? NEGV : vals[h];
    }
    __syncthreads();

    // ---------------- Phase 1b: per-head softmax (one warp per head) -------
    {
        float* row = s_compat + warp * NN;
        float mx = -3.4e38f;
        for (int n = lane; n < NN; n += 32) mx = fmaxf(mx, row[n]);
        #pragma unroll
        for (int o = 16; o > 0; o >>= 1) mx = fmaxf(mx, __shfl_xor_sync(0xffffffffu, mx, o));
        float sm = 0.f;
        for (int n = lane; n < NN; n += 32) {
            float ev = expf(row[n] - mx);
            row[n] = ev; sm += ev;
        }
        #pragma unroll
        for (int o = 16; o > 0; o >>= 1) sm += __shfl_xor_sync(0xffffffffu, sm, o);
        float inv = 1.0f / sm;
        for (int n = lane; n < NN; n += 32) row[n] *= inv;
    }
    __syncthreads();

    // ---------------- Phase 2: ebar[h] = sum_n attn[h][n] * emb[n] ---------
    {
        const float* at = s_compat + warp * NN;
        unsigned long long a0x = 0, a0y = 0, a1x = 0, a1y = 0;
        unsigned long long a2x = 0, a2y = 0, a3x = 0, a3y = 0;
        for (int n = 0; n < NN; n += 4) {
            unsigned long long p0 = packdup(at[n]);
            unsigned long long p1 = packdup(at[n + 1]);
            unsigned long long p2 = packdup(at[n + 2]);
            unsigned long long p3 = packdup(at[n + 3]);
            ulonglong2 e0 = ((const ulonglong2*)(embB + (size_t)n * DD))[lane];
            ulonglong2 e1 = ((const ulonglong2*)(embB + (size_t)(n + 1) * DD))[lane];
            ulonglong2 e2 = ((const ulonglong2*)(embB + (size_t)(n + 2) * DD))[lane];
            ulonglong2 e3 = ((const ulonglong2*)(embB + (size_t)(n + 3) * DD))[lane];
            a0x = fma2(p0, e0.x, a0x); a0y = fma2(p0, e0.y, a0y);
            a1x = fma2(p1, e1.x, a1x); a1y = fma2(p1, e1.y, a1y);
            a2x = fma2(p2, e2.x, a2x); a2y = fma2(p2, e2.y, a2y);
            a3x = fma2(p3, e3.x, a3x); a3y = fma2(p3, e3.y, a3y);
        }
        float2 fx = unpack2(add2(add2(a0x, a1x), add2(a2x, a3x)));
        float2 fy = unpack2(add2(add2(a0y, a1y), add2(a2y, a3y)));
        ((float4*)(s_ebar + warp * DD))[lane] = make_float4(fx.x, fx.y, fy.x, fy.y);
    }
    __syncthreads();

    // ------------- Phase 2b: heads -> glimpse -> gtilde (small matvecs) ----
    if (t < DD) {   // heads[h*16+k] = ebar_h . W_V[:, h*16+k]
        int h = t >> 4;
        const float* eb = s_ebar + h * DD;
        float acc = 0.f;
        for (int d = 0; d < DD; d++) acc += eb[d] * Wn[d * 384 + 128 + t];
        s_heads[t] = acc;
    }
    __syncthreads();
    if (t < DD) {   // glimpse = heads @ W_out
        float acc = 0.f;
        for (int i = 0; i < DD; i++) acc += s_heads[i] * Wo[i * DD + t];
        s_gl[t] = acc;
    }
    __syncthreads();
    if (t < DD) {   // gtilde[d] = W_L[d,:] . glimpse / sqrt(D)
        const float* w = Wn + t * 384 + 256;
        float acc = 0.f;
        for (int j = 0; j < DD; j++) acc += w[j] * s_gl[j];
        s_gt[t] = acc * 0.08838834764831845f;   // 1/sqrt(128)
    }
    __syncthreads();

    // ---------------- Phase 3: logits + log_softmax ------------------------
    float lmax = -3.4e38f;
    for (int n = t; n < NN; n += 256) {
        const ulonglong2* e2p = (const ulonglong2*)(embB + (size_t)n * DD);
        const ulonglong2* g2p = (const ulonglong2*)s_gt;
        unsigned long long a0 = 0, a1 = 0, b0 = 0, b1 = 0;
        #pragma unroll 8
        for (int j = 0; j < 32; j += 2) {
            ulonglong2 e = e2p[j], g = g2p[j];
            a0 = fma2(e.x, g.x, a0); a1 = fma2(e.y, g.y, a1);
            ulonglong2 e1 = e2p[j + 1], g1 = g2p[j + 1];
            b0 = fma2(e1.x, g1.x, b0); b1 = fma2(e1.y, g1.y, b1);
        }
        float2 r = unpack2(add2(add2(a0, b0), add2(a1, b1)));
        float v = tanhf(r.x + r.y) * 10.0f;
        if (mkB[n] != 0) v = NEGV;
        s_compat[n] = v;
        lmax = fmaxf(lmax, v);
    }
    #pragma unroll
    for (int o = 16; o > 0; o >>= 1) lmax = fmaxf(lmax, __shfl_xor_sync(0xffffffffu, lmax, o));
    if (lane == 0) s_red[warp] = lmax;
    __syncthreads();
    float bmax = s_red[0];
    #pragma unroll
    for (int w = 1; w < 8; w++) bmax = fmaxf(bmax, s_red[w]);
    float ls = 0.f;
    for (int n = t; n < NN; n += 256) ls += expf(s_compat[n] - bmax);
    #pragma unroll
    for (int o = 16; o > 0; o >>= 1) ls += __shfl_xor_sync(0xffffffffu, ls, o);
    if (lane == 0) s_red[8 + warp] = ls;
    __syncthreads();
    float tot = s_red[8];
    #pragma unroll
    for (int w = 1; w < 8; w++) tot += s_red[8 + w];
    float logZ = bmax + logf(tot);
    float* outB = out + (size_t)b * NN;
    for (int n = t; n < NN; n += 256) outB[n] = s_compat[n] - logZ;
}

extern "C" void kernel_launch(void* const* d_in, const int* in_sizes, int n_in,
                              void* d_out, int out_size) {
    const float* emb = (const float*)d_in[0];
    const float* Wn  = (const float*)d_in[1];
    const float* Wf  = (const float*)d_in[2];
    const float* Ws  = (const float*)d_in[3];
    const float* Wo  = (const float*)d_in[4];
    const int* fidx  = (const int*)d_in[5];
    const int* lidx  = (const int*)d_in[6];
    const int* mask  = (const int*)d_in[7];
    float* out = (float*)d_out;
    attn_fused_kernel<<<BB, 256>>>(emb, Wn, Wf, Ws, Wo, fidx, lidx, mask, out);
}

// round 4
// speedup vs baseline: 1.1693x; 1.1693x over previous
#include <cuda_runtime.h>

#define NN 1000
#define DD 128
#define NEGV (-1e9f)
typedef unsigned long long u64;

static __device__ __forceinline__ u64 pack2(float a, float b) {
    u64 r; asm("mov.b64 %0, {%1, %2};" : "=l"(r) : "f"(a), "f"(b)); return r;
}
static __device__ __forceinline__ u64 packdup(float a) { return pack2(a, a); }
static __device__ __forceinline__ u64 fma2(u64 a, u64 b, u64 c) {
    u64 d; asm("fma.rn.f32x2 %0, %1, %2, %3;" : "=l"(d) : "l"(a), "l"(b), "l"(c)); return d;
}
static __device__ __forceinline__ float2 unpack2(u64 v) {
    float lo, hi; asm("mov.b64 {%0, %1}, %2;" : "=f"(lo), "=f"(hi) : "l"(v));
    return make_float2(lo, hi);
}
static __device__ __forceinline__ float tanh_fast(float x) {
    float y; asm("tanh.approx.f32 %0, %1;" : "=f"(y) : "f"(x)); return y;
}

// smem word offsets
#define O_COMPAT 0          // 8000  (also s_part 2048, s_lg 1000)
#define O_BUF    8000       // 9216 = 256*36  (also s_at 8000)
#define O_QT     17216      // 1024 = 128*8  qt[d][h]
#define O_MEAN   18240
#define O_Q      18368
#define O_EF     18496
#define O_EL     18624
#define O_HEADS  18752
#define O_GL     18880
#define O_GT     19008
#define O_EBAR   19136      // 1024
#define O_RED    20160      // 32
#define SM_WORDS 20192      // 80768 bytes

__global__ __launch_bounds__(256) void attn_v3(
    const float* __restrict__ emb, const float* __restrict__ Wn,
    const float* __restrict__ Wf, const float* __restrict__ Ws,
    const float* __restrict__ Wo, const int* __restrict__ fidx,
    const int* __restrict__ lidx, const int* __restrict__ mask,
    float* __restrict__ out)
{
    extern __shared__ float sm[];
    float* s_compat = sm + O_COMPAT;
    float* s_buf    = sm + O_BUF;
    float* s_QT     = sm + O_QT;
    float* s_mean   = sm + O_MEAN;
    float* s_q      = sm + O_Q;
    float* s_ef     = sm + O_EF;
    float* s_el     = sm + O_EL;
    float* s_heads  = sm + O_HEADS;
    float* s_gl     = sm + O_GL;
    float* s_gt     = sm + O_GT;
    float* s_ebar   = sm + O_EBAR;
    float* s_red    = sm + O_RED;

    const int b = blockIdx.x, t = threadIdx.x;
    const int lane = t & 31, warp = t >> 5;
    const float* embB = emb + (size_t)b * NN * DD;
    const int* mkB = mask + (size_t)b * NN;

    // ---- Phase 0: mean + first/last rows ----
    {
        int d = t & 127, g = t >> 7;
        float a0 = 0.f, a1 = 0.f;
        int n = g;
        for (; n + 2 < NN; n += 4) {
            a0 += embB[(size_t)n * DD + d];
            a1 += embB[(size_t)(n + 2) * DD + d];
        }
        if (n < NN) a0 += embB[(size_t)n * DD + d];
        s_compat[g * DD + d] = a0 + a1;
    }
    if (t < DD) s_ef[t] = embB[(size_t)fidx[b] * DD + t];
    else        s_el[t - DD] = embB[(size_t)lidx[b] * DD + (t - DD)];
    __syncthreads();
    if (t < DD) s_mean[t] = (s_compat[t] + s_compat[DD + t]) * (1.0f / NN);
    __syncthreads();

    // ---- Phase 0b: q = mean@Wf + [ef;el]@Ws ----
    if (t < DD) {
        float acc = 0.f;
        #pragma unroll 4
        for (int i = 0; i < DD; i++) acc += s_mean[i] * Wf[i * DD + t];
        #pragma unroll 4
        for (int i = 0; i < DD; i++) acc += s_ef[i] * Ws[i * DD + t];
        #pragma unroll 4
        for (int i = 0; i < DD; i++) acc += s_el[i] * Ws[(DD + i) * DD + t];
        s_q[t] = acc;
    }
    __syncthreads();

    // ---- Phase 0c: qt[d][h] = 0.25 * W_K[d, h*16:+16] . q[h*16:+16] ----
    {
        int d = t >> 1, h0 = (t & 1) * 4;
        #pragma unroll
        for (int h = h0; h < h0 + 4; h++) {
            const float* w = Wn + d * 384 + h * 16;
            const float* qq = s_q + h * 16;
            float acc = 0.f;
            #pragma unroll
            for (int k = 0; k < 16; k++) acc += w[k] * qq[k];
            s_QT[d * 8 + h] = acc * 0.25f;
        }
    }

    // ---- Phase 1: compat via smem-staged chunks ----
    for (int T = 0; T < 4; T++) {
        u64 a0 = 0, a1 = 0, a2 = 0, a3 = 0;
        for (int c = 0; c < 4; c++) {
            __syncthreads();
            #pragma unroll
            for (int k = 0; k < 8; k++) {
                int i = (k << 8) + t;
                int rl = i >> 3, seg = i & 7;
                int gr = T * 256 + rl; if (gr > NN - 1) gr = NN - 1;
                *(float4*)(s_buf + rl * 36 + seg * 4) =
                    *(const float4*)(embB + (size_t)gr * DD + c * 32 + seg * 4);
            }
            __syncthreads();
            const float* bp = s_buf + t * 36;
            const u64* qtp = (const u64*)s_QT + c * 128;
            #pragma unroll
            for (int j = 0; j < 8; j++) {
                float4 e = *(const float4*)(bp + j * 4);
                const u64* q = qtp + j * 16;
                u64 d0 = packdup(e.x), d1 = packdup(e.y);
                u64 d2 = packdup(e.z), d3 = packdup(e.w);
                a0 = fma2(d0, q[0], a0);  a1 = fma2(d0, q[1], a1);
                a2 = fma2(d0, q[2], a2);  a3 = fma2(d0, q[3], a3);
                a0 = fma2(d1, q[4], a0);  a1 = fma2(d1, q[5], a1);
                a2 = fma2(d1, q[6], a2);  a3 = fma2(d1, q[7], a3);
                a0 = fma2(d2, q[8], a0);  a1 = fma2(d2, q[9], a1);
                a2 = fma2(d2, q[10], a2); a3 = fma2(d2, q[11], a3);
                a0 = fma2(d3, q[12], a0); a1 = fma2(d3, q[13], a1);
                a2 = fma2(d3, q[14], a2); a3 = fma2(d3, q[15], a3);
            }
        }
        int row = T * 256 + t;
        if (row < NN) {
            int mk = mkB[row];
            float2 p0 = unpack2(a0), p1 = unpack2(a1);
            float2 p2 = unpack2(a2), p3 = unpack2(a3);
            float v[8] = {p0.x, p0.y, p1.x, p1.y, p2.x, p2.y, p3.x, p3.y};
            #pragma unroll
            for (int h = 0; h < 8; h++)
                s_compat[h * NN + row] = mk ? NEGV : v[h];
        }
    }
    __syncthreads();

    // ---- Phase 1b: per-head softmax (warp = head), write s_at[n][8] ----
    {
        float* row = s_compat + warp * NN;
        float mx = -1e30f;
        for (int n = lane; n < NN; n += 32) mx = fmaxf(mx, row[n]);
        #pragma unroll
        for (int o = 16; o > 0; o >>= 1) mx = fmaxf(mx, __shfl_xor_sync(0xffffffffu, mx, o));
        float sme = 0.f;
        for (int n = lane; n < NN; n += 32) sme += __expf(row[n] - mx);
        #pragma unroll
        for (int o = 16; o > 0; o >>= 1) sme += __shfl_xor_sync(0xffffffffu, sme, o);
        float inv = 1.0f / sme;
        for (int n = lane; n < NN; n += 32)
            s_buf[n * 8 + warp] = __expf(row[n] - mx) * inv;   // s_at
    }
    __syncthreads();

    // ---- Phase 2: ebar[h][d] = sum_n attn[h][n]*emb[n][d], single pass ----
    {
        int dim = t & 127, g = t >> 7;
        u64 a0 = 0, a1 = 0, a2 = 0, a3 = 0;
        #pragma unroll 4
        for (int n = g; n < NN; n += 2) {
            float e = embB[(size_t)n * DD + dim];
            const u64* at = (const u64*)(s_buf + n * 8);
            u64 ed = packdup(e);
            a0 = fma2(ed, at[0], a0); a1 = fma2(ed, at[1], a1);
            a2 = fma2(ed, at[2], a2); a3 = fma2(ed, at[3], a3);
        }
        float2 f0 = unpack2(a0), f1 = unpack2(a1), f2 = unpack2(a2), f3 = unpack2(a3);
        float* pp = s_compat + g * 1024 + dim;   // s_part[g][h][128]
        pp[0] = f0.x; pp[128] = f0.y; pp[256] = f1.x; pp[384] = f1.y;
        pp[512] = f2.x; pp[640] = f2.y; pp[768] = f3.x; pp[896] = f3.y;
    }
    __syncthreads();
    #pragma unroll
    for (int k = 0; k < 4; k++) {
        int i = k * 256 + t;
        s_ebar[i] = s_compat[i] + s_compat[1024 + i];
    }
    __syncthreads();

    // ---- Phase 2b: heads -> glimpse -> gtilde ----
    if (t < DD) {
        int h = t >> 4;
        const float* eb = s_ebar + h * DD;
        float acc = 0.f;
        #pragma unroll 4
        for (int d = 0; d < DD; d++) acc += eb[d] * Wn[d * 384 + 128 + t];
        s_heads[t] = acc;
    }
    __syncthreads();
    if (t < DD) {
        float acc = 0.f;
        #pragma unroll 4
        for (int i = 0; i < DD; i++) acc += s_heads[i] * Wo[i * DD + t];
        s_gl[t] = acc;
    }
    __syncthreads();
    if (t < DD) {
        const float* w = Wn + t * 384 + 256;
        float acc = 0.f;
        #pragma unroll 4
        for (int j = 0; j < DD; j++) acc += w[j] * s_gl[j];
        s_gt[t] = acc * 0.08838834764831845f;
    }
    __syncthreads();

    // ---- Phase 3: logits via smem-staged chunks + log_softmax ----
    float lmax = -1e30f;
    for (int T = 0; T < 4; T++) {
        u64 acc = 0;
        for (int c = 0; c < 4; c++) {
            __syncthreads();
            #pragma unroll
            for (int k = 0; k < 8; k++) {
                int i = (k << 8) + t;
                int rl = i >> 3, seg = i & 7;
                int gr = T * 256 + rl; if (gr > NN - 1) gr = NN - 1;
                *(float4*)(s_buf + rl * 36 + seg * 4) =
                    *(const float4*)(embB + (size_t)gr * DD + c * 32 + seg * 4);
            }
            __syncthreads();
            const float* bp = s_buf + t * 36;
            const u64* gt = (const u64*)s_gt + c * 16;
            #pragma unroll
            for (int j = 0; j < 8; j++) {
                float4 e = *(const float4*)(bp + j * 4);
                acc = fma2(pack2(e.x, e.y), gt[j * 2], acc);
                acc = fma2(pack2(e.z, e.w), gt[j * 2 + 1], acc);
            }
        }
        int row = T * 256 + t;
        if (row < NN) {
            float2 r = unpack2(acc);
            float v = tanh_fast(r.x + r.y) * 10.0f;
            if (mkB[row] != 0) v = NEGV;
            s_compat[row] = v;                    // s_lg
            lmax = fmaxf(lmax, v);
        }
    }
    __syncthreads();
    #pragma unroll
    for (int o = 16; o > 0; o >>= 1) lmax = fmaxf(lmax, __shfl_xor_sync(0xffffffffu, lmax, o));
    if (lane == 0) s_red[warp] = lmax;
    __syncthreads();
    float bmax = s_red[0];
    #pragma unroll
    for (int w = 1; w < 8; w++) bmax = fmaxf(bmax, s_red[w]);
    float ls = 0.f;
    for (int n = t; n < NN; n += 256) ls += __expf(s_compat[n] - bmax);
    #pragma unroll
    for (int o = 16; o > 0; o >>= 1) ls += __shfl_xor_sync(0xffffffffu, ls, o);
    if (lane == 0) s_red[8 + warp] = ls;
    __syncthreads();
    float tot = s_red[8];
    #pragma unroll
    for (int w = 1; w < 8; w++) tot += s_red[8 + w];
    float logZ = bmax + logf(tot);
    float* outB = out + (size_t)b * NN;
    for (int n = t; n < NN; n += 256) outB[n] = s_compat[n] - logZ;
}

extern "C" void kernel_launch(void* const* d_in, const int* in_sizes, int n_in,
                              void* d_out, int out_size) {
    const float* emb = (const float*)d_in[0];
    const float* Wn  = (const float*)d_in[1];
    const float* Wf  = (const float*)d_in[2];
    const float* Ws  = (const float*)d_in[3];
    const float* Wo  = (const float*)d_in[4];
    const int* fidx  = (const int*)d_in[5];
    const int* lidx  = (const int*)d_in[6];
    const int* mask  = (const int*)d_in[7];
    float* out = (float*)d_out;
    static_assert(SM_WORDS * 4 == 80768, "");
    cudaFuncSetAttribute(attn_v3, cudaFuncAttributeMaxDynamicSharedMemorySize, 80768);
    attn_v3<<<256, 256, 80768>>>(emb, Wn, Wf, Ws, Wo, fidx, lidx, mask, out);
}

// round 5
// speedup vs baseline: 1.4573x; 1.2463x over previous
#include <cuda_runtime.h>

#define NN 1000
#define DD 128
#define NEGV (-1e9f)
typedef unsigned long long u64;

static __device__ __forceinline__ u64 pack2(float a, float b) {
    u64 r; asm("mov.b64 %0, {%1, %2};" : "=l"(r) : "f"(a), "f"(b)); return r;
}
static __device__ __forceinline__ u64 packdup(float a) { return pack2(a, a); }
static __device__ __forceinline__ u64 fma2(u64 a, u64 b, u64 c) {
    u64 d; asm("fma.rn.f32x2 %0, %1, %2, %3;" : "=l"(d) : "l"(a), "l"(b), "l"(c)); return d;
}
static __device__ __forceinline__ float2 unpack2(u64 v) {
    float lo, hi; asm("mov.b64 {%0, %1}, %2;" : "=f"(lo), "=f"(hi) : "l"(v));
    return make_float2(lo, hi);
}
static __device__ __forceinline__ float tanh_fast(float x) {
    float y; asm("tanh.approx.f32 %0, %1;" : "=f"(y) : "f"(x)); return y;
}

// smem word offsets
#define O_COMPAT 0          // 8000  (later: phase2 partials 4096 / s_lg 1000 + s_p2 512)
#define O_BUF    8000       // 9216 = 256*36  (later: s_at 8000)
#define O_QT     17216      // 1024 = qt[d][8]
#define O_MEAN   18240
#define O_Q      18368
#define O_EF     18496
#define O_EL     18624
#define O_HEADS  18752
#define O_GL     18880
#define O_GT     19008
#define O_EBAR   19136      // 1024
#define O_RED    20160      // 32
#define SM_WORDS 20192      // 80768 bytes

__global__ __launch_bounds__(512, 2) void attn_v4(
    const float* __restrict__ emb, const float* __restrict__ Wn,
    const float* __restrict__ Wf, const float* __restrict__ Ws,
    const float* __restrict__ Wo, const int* __restrict__ fidx,
    const int* __restrict__ lidx, const int* __restrict__ mask,
    float* __restrict__ out)
{
    extern __shared__ float sm[];
    float* s_compat = sm + O_COMPAT;
    float* s_buf    = sm + O_BUF;
    float* s_QT     = sm + O_QT;
    float* s_mean   = sm + O_MEAN;
    float* s_q      = sm + O_Q;
    float* s_ef     = sm + O_EF;
    float* s_el     = sm + O_EL;
    float* s_heads  = sm + O_HEADS;
    float* s_gl     = sm + O_GL;
    float* s_gt     = sm + O_GT;
    float* s_ebar   = sm + O_EBAR;
    float* s_red    = sm + O_RED;

    const int b = blockIdx.x, t = threadIdx.x;
    const int lane = t & 31, warp = t >> 5;
    const float* embB = emb + (size_t)b * NN * DD;
    const int* mkB = mask + (size_t)b * NN;

    // ---- Phase 0: mean (4 row-groups, 16 rows in flight) + first/last ----
    {
        int d = t & 127, g = t >> 7;               // g in 0..3
        const float* E = embB + d;
        float a0 = 0.f, a1 = 0.f, a2 = 0.f, a3 = 0.f;
        int n = g;
        for (; n + 12 < NN; n += 16) {
            a0 += E[(size_t)n * DD];
            a1 += E[(size_t)(n + 4) * DD];
            a2 += E[(size_t)(n + 8) * DD];
            a3 += E[(size_t)(n + 12) * DD];
        }
        for (; n < NN; n += 4) a0 += E[(size_t)n * DD];
        s_compat[g * DD + d] = (a0 + a1) + (a2 + a3);
    }
    if (t < DD)       s_ef[t] = embB[(size_t)fidx[b] * DD + t];
    else if (t < 256) s_el[t - DD] = embB[(size_t)lidx[b] * DD + (t - DD)];
    __syncthreads();
    if (t < DD)
        s_mean[t] = (s_compat[t] + s_compat[DD + t] + s_compat[2 * DD + t]
                     + s_compat[3 * DD + t]) * (1.0f / NN);
    __syncthreads();

    // ---- Phase 0b: q = mean@Wf + [ef;el]@Ws ----
    if (t < DD) {
        float acc = 0.f;
        #pragma unroll 4
        for (int i = 0; i < DD; i++) acc += s_mean[i] * Wf[i * DD + t];
        #pragma unroll 4
        for (int i = 0; i < DD; i++) acc += s_ef[i] * Ws[i * DD + t];
        #pragma unroll 4
        for (int i = 0; i < DD; i++) acc += s_el[i] * Ws[(DD + i) * DD + t];
        s_q[t] = acc;
    }
    __syncthreads();

    // ---- Phase 0c: qt[d][h] = 0.25 * W_K[d, h*16:+16] . q[h*16:+16] ----
    if (t < 256) {
        int d = t >> 1, h0 = (t & 1) * 4;
        #pragma unroll
        for (int h = h0; h < h0 + 4; h++) {
            const float* w = Wn + d * 384 + h * 16;
            const float* qq = s_q + h * 16;
            float acc = 0.f;
            #pragma unroll
            for (int k = 0; k < 16; k++) acc += w[k] * qq[k];
            s_QT[d * 8 + h] = acc * 0.25f;
        }
    }

    // ---- Phase 1: compat, 2 threads/row (4 heads each), smem-staged ----
    {
        const int r = t >> 1, q4 = t & 1;
        for (int T = 0; T < 4; T++) {
            u64 acc01 = 0, acc23 = 0;
            for (int c = 0; c < 4; c++) {
                __syncthreads();
                #pragma unroll
                for (int k = 0; k < 4; k++) {
                    int i = (k << 9) + t;
                    int rl = i >> 3, seg = i & 7;
                    int gr = T * 256 + rl; if (gr > NN - 1) gr = NN - 1;
                    *(float4*)(s_buf + rl * 36 + seg * 4) =
                        *(const float4*)(embB + (size_t)gr * DD + c * 32 + seg * 4);
                }
                __syncthreads();
                const float* bp = s_buf + r * 36;
                const ulonglong2* qt2 = (const ulonglong2*)s_QT + q4;  // [d] stride 2
                #pragma unroll
                for (int j = 0; j < 8; j++) {
                    float4 e = *(const float4*)(bp + j * 4);
                    int d0 = (c * 32 + j * 4) * 2;
                    ulonglong2 qa;
                    qa = qt2[d0];     acc01 = fma2(packdup(e.x), qa.x, acc01);
                                      acc23 = fma2(packdup(e.x), qa.y, acc23);
                    qa = qt2[d0 + 2]; acc01 = fma2(packdup(e.y), qa.x, acc01);
                                      acc23 = fma2(packdup(e.y), qa.y, acc23);
                    qa = qt2[d0 + 4]; acc01 = fma2(packdup(e.z), qa.x, acc01);
                                      acc23 = fma2(packdup(e.z), qa.y, acc23);
                    qa = qt2[d0 + 6]; acc01 = fma2(packdup(e.w), qa.x, acc01);
                                      acc23 = fma2(packdup(e.w), qa.y, acc23);
                }
            }
            int row = T * 256 + r;
            if (row < NN) {
                int mk = mkB[row];
                float2 p01 = unpack2(acc01), p23 = unpack2(acc23);
                int hb = q4 * 4;
                s_compat[(hb + 0) * NN + row] = mk ? NEGV : p01.x;
                s_compat[(hb + 1) * NN + row] = mk ? NEGV : p01.y;
                s_compat[(hb + 2) * NN + row] = mk ? NEGV : p23.x;
                s_compat[(hb + 3) * NN + row] = mk ? NEGV : p23.y;
            }
        }
    }
    __syncthreads();

    // ---- Phase 1b: per-head softmax, 2 warps per head ----
    {
        int h = warp >> 1, seg = warp & 1;
        const float* row = s_compat + h * NN;
        float mx = -1e30f;
        for (int n = seg * 32 + lane; n < NN; n += 64) mx = fmaxf(mx, row[n]);
        #pragma unroll
        for (int o = 16; o > 0; o >>= 1) mx = fmaxf(mx, __shfl_xor_sync(0xffffffffu, mx, o));
        if (lane == 0) s_red[warp] = mx;
        __syncthreads();
        float hm = fmaxf(s_red[2 * h], s_red[2 * h + 1]);
        float sme = 0.f;
        for (int n = seg * 32 + lane; n < NN; n += 64) sme += __expf(row[n] - hm);
        #pragma unroll
        for (int o = 16; o > 0; o >>= 1) sme += __shfl_xor_sync(0xffffffffu, sme, o);
        if (lane == 0) s_red[16 + warp] = sme;
        __syncthreads();
        float inv = 1.0f / (s_red[16 + 2 * h] + s_red[16 + 2 * h + 1]);
        for (int n = seg * 32 + lane; n < NN; n += 64)
            s_buf[n * 8 + h] = __expf(row[n] - hm) * inv;   // s_at[n][8]
    }
    __syncthreads();

    // ---- Phase 2: ebar, 4 row-groups, attn broadcast, unroll x4 ----
    {
        int dim = t & 127, g = t >> 7;
        const float* E = embB + dim;
        u64 a0 = 0, a1 = 0, a2 = 0, a3 = 0;
        int n = g;
        for (; n + 12 < NN; n += 16) {
            float e0 = E[(size_t)n * DD];
            float e1 = E[(size_t)(n + 4) * DD];
            float e2 = E[(size_t)(n + 8) * DD];
            float e3 = E[(size_t)(n + 12) * DD];
            const u64* t0 = (const u64*)(s_buf + n * 8);
            const u64* t1 = (const u64*)(s_buf + (n + 4) * 8);
            const u64* t2 = (const u64*)(s_buf + (n + 8) * 8);
            const u64* t3 = (const u64*)(s_buf + (n + 12) * 8);
            u64 d0 = packdup(e0), d1 = packdup(e1), d2 = packdup(e2), d3 = packdup(e3);
            a0 = fma2(d0, t0[0], a0); a1 = fma2(d0, t0[1], a1);
            a2 = fma2(d0, t0[2], a2); a3 = fma2(d0, t0[3], a3);
            a0 = fma2(d1, t1[0], a0); a1 = fma2(d1, t1[1], a1);
            a2 = fma2(d1, t1[2], a2); a3 = fma2(d1, t1[3], a3);
            a0 = fma2(d2, t2[0], a0); a1 = fma2(d2, t2[1], a1);
            a2 = fma2(d2, t2[2], a2); a3 = fma2(d2, t2[3], a3);
            a0 = fma2(d3, t3[0], a0); a1 = fma2(d3, t3[1], a1);
            a2 = fma2(d3, t3[2], a2); a3 = fma2(d3, t3[3], a3);
        }
        for (; n < NN; n += 4) {
            u64 ed = packdup(E[(size_t)n * DD]);
            const u64* at = (const u64*)(s_buf + n * 8);
            a0 = fma2(ed, at[0], a0); a1 = fma2(ed, at[1], a1);
            a2 = fma2(ed, at[2], a2); a3 = fma2(ed, at[3], a3);
        }
        __syncthreads();   // compat region free now
        float2 f0 = unpack2(a0), f1 = unpack2(a1), f2 = unpack2(a2), f3 = unpack2(a3);
        float* pp = s_compat + g * 1024 + dim;   // partials [g][h][128]
        pp[0] = f0.x; pp[128] = f0.y; pp[256] = f1.x; pp[384] = f1.y;
        pp[512] = f2.x; pp[640] = f2.y; pp[768] = f3.x; pp[896] = f3.y;
    }
    __syncthreads();
    {
        int i = t;
        if (i < 1024)
            s_ebar[i] = (s_compat[i] + s_compat[1024 + i])
                      + (s_compat[2048 + i] + s_compat[3072 + i]);
        int i2 = t + 512;
        s_ebar[i2] = (s_compat[i2] + s_compat[1024 + i2])
                   + (s_compat[2048 + i2] + s_compat[3072 + i2]);
    }
    __syncthreads();

    // ---- Phase 2b: heads -> glimpse -> gtilde ----
    if (t < DD) {
        int h = t >> 4;
        const float* eb = s_ebar + h * DD;
        float acc = 0.f;
        #pragma unroll 4
        for (int d = 0; d < DD; d++) acc += eb[d] * Wn[d * 384 + 128 + t];
        s_heads[t] = acc;
    }
    __syncthreads();
    if (t < DD) {
        float acc = 0.f;
        #pragma unroll 4
        for (int i = 0; i < DD; i++) acc += s_heads[i] * Wo[i * DD + t];
        s_gl[t] = acc;
    }
    __syncthreads();
    if (t < DD) {
        const float* w = Wn + t * 384 + 256;
        float acc = 0.f;
        #pragma unroll 4
        for (int j = 0; j < DD; j++) acc += w[j] * s_gl[j];
        s_gt[t] = acc * 0.08838834764831845f;
    }
    __syncthreads();

    // ---- Phase 3: logits, 2 threads/row (dim split), staged ----
    float* s_lg = s_compat;            // 1000
    float* s_p2 = s_compat + 1024;     // 512
    float lmax = -1e30f;
    {
        int r = t & 255, half = t >> 8;
        for (int T = 0; T < 4; T++) {
            u64 acc = 0;
            for (int c = 0; c < 4; c++) {
                __syncthreads();
                #pragma unroll
                for (int k = 0; k < 4; k++) {
                    int i = (k << 9) + t;
                    int rl = i >> 3, seg = i & 7;
                    int gr = T * 256 + rl; if (gr > NN - 1) gr = NN - 1;
                    *(float4*)(s_buf + rl * 36 + seg * 4) =
                        *(const float4*)(embB + (size_t)gr * DD + c * 32 + seg * 4);
                }
                __syncthreads();
                if ((c >> 1) == half) {
                    const float* bp = s_buf + r * 36;
                    const u64* gt = (const u64*)s_gt + c * 16;
                    #pragma unroll
                    for (int j = 0; j < 8; j++) {
                        float4 e = *(const float4*)(bp + j * 4);
                        acc = fma2(pack2(e.x, e.y), gt[j * 2], acc);
                        acc = fma2(pack2(e.z, e.w), gt[j * 2 + 1], acc);
                    }
                }
            }
            float2 rr = unpack2(acc);
            s_p2[half * 256 + r] = rr.x + rr.y;
            __syncthreads();
            int row = T * 256 + t;
            if (t < 256 && row < NN) {
                float v = tanh_fast(s_p2[t] + s_p2[256 + t]) * 10.0f;
                if (mkB[row] != 0) v = NEGV;
                s_lg[row] = v;
                lmax = fmaxf(lmax, v);
            }
            __syncthreads();
        }
    }
    // ---- log-softmax over 1000 ----
    #pragma unroll
    for (int o = 16; o > 0; o >>= 1) lmax = fmaxf(lmax, __shfl_xor_sync(0xffffffffu, lmax, o));
    if (lane == 0) s_red[warp] = lmax;
    __syncthreads();
    float bmax = s_red[0];
    #pragma unroll
    for (int w = 1; w < 16; w++) bmax = fmaxf(bmax, s_red[w]);
    float ls = 0.f;
    for (int n = t; n < NN; n += 512) ls += __expf(s_lg[n] - bmax);
    #pragma unroll
    for (int o = 16; o > 0; o >>= 1) ls += __shfl_xor_sync(0xffffffffu, ls, o);
    if (lane == 0) s_red[16 + warp] = ls;
    __syncthreads();
    float tot = s_red[16];
    #pragma unroll
    for (int w = 1; w < 16; w++) tot += s_red[16 + w];
    float logZ = bmax + logf(tot);
    float* outB = out + (size_t)b * NN;
    for (int n = t; n < NN; n += 512) outB[n] = s_lg[n] - logZ;
}

extern "C" void kernel_launch(void* const* d_in, const int* in_sizes, int n_in,
                              void* d_out, int out_size) {
    const float* emb = (const float*)d_in[0];
    const float* Wn  = (const float*)d_in[1];
    const float* Wf  = (const float*)d_in[2];
    const float* Ws  = (const float*)d_in[3];
    const float* Wo  = (const float*)d_in[4];
    const int* fidx  = (const int*)d_in[5];
    const int* lidx  = (const int*)d_in[6];
    const int* mask  = (const int*)d_in[7];
    float* out = (float*)d_out;
    cudaFuncSetAttribute(attn_v4, cudaFuncAttributeMaxDynamicSharedMemorySize, SM_WORDS * 4);
    attn_v4<<<256, 512, SM_WORDS * 4>>>(emb, Wn, Wf, Ws, Wo, fidx, lidx, mask, out);
}